// round 14
// baseline (speedup 1.0000x reference)
#include <cuda_runtime.h>

// SSIM loss — R14: R13 pipeline at 288 threads x 5 blocks/SM (45 warps = 70%
// occ), single-round phase 1 (276 tasks), 128x16 tiles, per-task guards,
// two-field algebra, ticket-fused finish.

typedef unsigned long long u64;

#define TX 128
#define TY 16
#define HALO 5
#define INW 138                     // TX + 2*HALO
#define VS 139                      // u64 stride (odd; 139 mod 16 = 11 -> conflict-free)
#define NTHREADS 288
#define IMG 512
#define TILES_X 4
#define TILES_Y 32
#define PLANES 48
#define NBLOCKS (PLANES * TILES_Y * TILES_X)   // 6144
#define NPIX 12582912.0f

#define C1 1.0e-4f
#define C2 9.0e-4f

#define N_V (TY * VS)               // 2224 u64 per buffer

__device__ float g_partials[NBLOCKS];
__device__ unsigned g_ticket = 0;

// Normalized 1D Gaussian, window=11, sigma=1.5
__device__ __forceinline__ constexpr float Wt(int k) {
    constexpr float w[11] = {
        0.00102838f, 0.00759877f, 0.03600081f, 0.10936072f, 0.21300553f,
        0.26601169f,
        0.21300553f, 0.10936072f, 0.03600081f, 0.00759877f, 0.00102838f
    };
    return w[k];
}

// ---- f32x2 packed helpers ----
__device__ __forceinline__ u64 pk(float lo, float hi) {
    u64 r; asm("mov.b64 %0, {%1, %2};" : "=l"(r) : "f"(lo), "f"(hi)); return r;
}
__device__ __forceinline__ float2 upk(u64 v) {
    float2 r; asm("mov.b64 {%0, %1}, %2;" : "=f"(r.x), "=f"(r.y) : "l"(v)); return r;
}
__device__ __forceinline__ u64 fma2(u64 a, u64 b, u64 c) {
    u64 d; asm("fma.rn.f32x2 %0, %1, %2, %3;" : "=l"(d) : "l"(a), "l"(b), "l"(c)); return d;
}
__device__ __forceinline__ u64 mul2(u64 a, u64 b) {
    u64 d; asm("mul.rn.f32x2 %0, %1, %2;" : "=l"(d) : "l"(a), "l"(b)); return d;
}
__device__ __forceinline__ u64 wsel(const u64 (&w)[6], int k) {
    return w[k < 6 ? k : 10 - k];
}

// Vertical-blur task: WIN input rows -> NOUT output rows for column c.
// Per-task guards: x-out -> zeros; y-window inside -> fast; else y-guarded.
template<int WIN, int NOUT>
__device__ __forceinline__ void vtask(
    const float* __restrict__ p_plane, const float* __restrict__ t_plane,
    int gx, int gybase,
    u64* __restrict__ s_VA, u64* __restrict__ s_VB,
    int y0, int c, const u64 (&w2)[6])
{
    if ((unsigned)gx >= IMG) {          // whole column out of image -> zeros
        #pragma unroll
        for (int j = 0; j < NOUT; j++) {
            s_VA[(y0 + j) * VS + c] = 0ull;
            s_VB[(y0 + j) * VS + c] = 0ull;
        }
        return;
    }

    u64 a[WIN];
    if ((unsigned)gybase <= (IMG - WIN)) {   // fast path: window fully inside
        const float* pp = p_plane + (long)gybase * IMG + gx;
        const float* tp = t_plane + (long)gybase * IMG + gx;
        #pragma unroll
        for (int i = 0; i < WIN; i++)
            a[i] = pk(__ldg(pp + i * IMG), __ldg(tp + i * IMG));
    } else {
        #pragma unroll
        for (int i = 0; i < WIN; i++) {
            int gy = gybase + i;
            float pv = 0.0f, tv = 0.0f;
            if ((unsigned)gy < IMG) {
                long o = (long)gy * IMG + gx;
                pv = __ldg(p_plane + o);
                tv = __ldg(t_plane + o);
            }
            a[i] = pk(pv, tv);
        }
    }
    #pragma unroll
    for (int j = 0; j < NOUT; j++) {
        u64 acc = mul2(wsel(w2, 0), a[j]);
        #pragma unroll
        for (int k = 1; k < 11; k++) acc = fma2(wsel(w2, k), a[j + k], acc);
        s_VA[(y0 + j) * VS + c] = acc;
    }
    #pragma unroll
    for (int i = 0; i < WIN; i++) {     // (p,t) -> (p^2+t^2, p*t)
        float2 v = upk(a[i]);
        a[i] = pk(fmaf(v.x, v.x, v.y * v.y), v.x * v.y);
    }
    #pragma unroll
    for (int j = 0; j < NOUT; j++) {
        u64 acc = mul2(wsel(w2, 0), a[j]);
        #pragma unroll
        for (int k = 1; k < 11; k++) acc = fma2(wsel(w2, k), a[j + k], acc);
        s_VB[(y0 + j) * VS + c] = acc;
    }
}

__global__ __launch_bounds__(NTHREADS, 5)
void ssim_tile_kernel(const float* __restrict__ pred,
                      const float* __restrict__ targ,
                      float* __restrict__ out) {
    __shared__ u64 s_VA[N_V];     // V-blurred (mu_p, mu_t)
    __shared__ u64 s_VB[N_V];     // V-blurred (E[p^2]+E[t^2], E[pt])
    __shared__ float s_warp[9];
    __shared__ int   s_last;

    const int tid = threadIdx.x;
    const int ox = blockIdx.x * TX;
    const int oy = blockIdx.y * TY;
    const long plane_base = (long)blockIdx.z * (IMG * IMG);
    const float* __restrict__ p_plane = pred + plane_base;
    const float* __restrict__ t_plane = targ + plane_base;

    u64 w2[6];
    #pragma unroll
    for (int k = 0; k < 6; k++) w2[k] = pk(Wt(k), Wt(k));

    // ---- Phase 1: vertical blur from global. SINGLE round.
    // 276 tasks = 138 halo-cols x 2 row-groups of 8 outputs (window 18).
    if (tid < INW * 2) {
        int c = tid % INW;
        int g = tid / INW;
        int gx = ox + c - HALO;
        int y0 = 8 * g;
        vtask<18, 8>(p_plane, t_plane, gx,
                     oy + y0 - HALO, s_VA, s_VB, y0, c, w2);
    }
    __syncthreads();

    // ---- Phase 2: horizontal blur + SSIM. 512 tasks of 4 cols.
    // Round 1: tasks 0..287; round 2: tasks 288..511.
    float local = 0.0f;
    #pragma unroll 1
    for (int it = 0; it < 2; it++) {
        const int task = tid + it * NTHREADS;
        if (task < 512) {
            const int r = task & 15;
            const int grp = task >> 4;          // 0..31
            const int base = r * VS + 4 * grp;

            u64 amu[4];
            {
                u64 h[14];
                #pragma unroll
                for (int i = 0; i < 14; i++) h[i] = s_VA[base + i];
                #pragma unroll
                for (int j = 0; j < 4; j++) {
                    u64 acc = mul2(wsel(w2, 0), h[j]);
                    #pragma unroll
                    for (int k = 1; k < 11; k++) acc = fma2(wsel(w2, k), h[j + k], acc);
                    amu[j] = acc;
                }
            }
            u64 asb[4];
            {
                u64 h[14];
                #pragma unroll
                for (int i = 0; i < 14; i++) h[i] = s_VB[base + i];
                #pragma unroll
                for (int j = 0; j < 4; j++) {
                    u64 acc = mul2(wsel(w2, 0), h[j]);
                    #pragma unroll
                    for (int k = 1; k < 11; k++) acc = fma2(wsel(w2, k), h[j + k], acc);
                    asb[j] = acc;
                }
            }
            #pragma unroll
            for (int j = 0; j < 4; j++) {
                float2 mu = upk(amu[j]);
                float2 sb = upk(asb[j]);        // (E[p^2]+E[t^2], E[pt])
                float mu_p2 = mu.x * mu.x;
                float mu_t2 = mu.y * mu.y;
                float mu_pt = mu.x * mu.y;
                float num = (2.0f * mu_pt + C1) * (2.0f * (sb.y - mu_pt) + C2);
                float den = (mu_p2 + mu_t2 + C1) * ((sb.x - mu_p2 - mu_t2) + C2);
                local += __fdividef(num, den);
            }
        }
    }

    // ---- Phase 3: block reduction (9 warps) ----
    float v = local;
    #pragma unroll
    for (int off = 16; off; off >>= 1)
        v += __shfl_xor_sync(0xFFFFFFFFu, v, off);
    if ((tid & 31) == 0) s_warp[tid >> 5] = v;
    __syncthreads();
    if (tid < 16) {
        v = (tid < 9) ? s_warp[tid] : 0.0f;
        #pragma unroll
        for (int off = 8; off; off >>= 1)
            v += __shfl_xor_sync(0x0000FFFFu, v, off);
    }
    if (tid == 0) {
        int bl = (blockIdx.z * TILES_Y + blockIdx.y) * TILES_X + blockIdx.x;
        g_partials[bl] = v;
        __threadfence();
        unsigned t = atomicInc(&g_ticket, NBLOCKS - 1);  // wraps -> self-reset
        s_last = (t == NBLOCKS - 1);
    }
    __syncthreads();

    // ---- Phase 4: last block folds partials (fixed order, deterministic) ----
    if (s_last) {
        float s = 0.0f;
        for (int i = tid; i < NBLOCKS; i += NTHREADS)
            s += __ldcg(&g_partials[i]);
        #pragma unroll
        for (int off = 16; off; off >>= 1)
            s += __shfl_xor_sync(0xFFFFFFFFu, s, off);
        if ((tid & 31) == 0) s_warp[tid >> 5] = s;
        __syncthreads();
        if (tid < 16) {
            s = (tid < 9) ? s_warp[tid] : 0.0f;
            #pragma unroll
            for (int off = 8; off; off >>= 1)
                s += __shfl_xor_sync(0x0000FFFFu, s, off);
            if (tid == 0) out[0] = 1.0f - s * (1.0f / NPIX);
        }
    }
}

extern "C" void kernel_launch(void* const* d_in, const int* in_sizes, int n_in,
                              void* d_out, int out_size) {
    const float* pred = (const float*)d_in[0];
    const float* targ = (const float*)d_in[1];
    float* out = (float*)d_out;

    dim3 grid(TILES_X, TILES_Y, PLANES);
    ssim_tile_kernel<<<grid, NTHREADS>>>(pred, targ, out);
}

// round 15
// speedup vs baseline: 1.0218x; 1.0218x over previous
#include <cuda_runtime.h>

// SSIM loss — R15: R13 pipeline at TX=64,TY=16 (smem 19.2KB -> ~130KB L1D
// carveout; phase-1 AND phase-2 single-round), per-task 3-way guards,
// two-field algebra, ticket-fused finish. 5 blocks/SM as R13.

typedef unsigned long long u64;

#define TX 64
#define TY 16
#define HALO 5
#define INW 74                      // TX + 2*HALO
#define VS 75                       // u64 stride (odd; 75 mod 16 = 11 -> conflict-free)
#define NTHREADS 256
#define IMG 512
#define TILES_X 8
#define TILES_Y 32
#define PLANES 48
#define NBLOCKS (PLANES * TILES_Y * TILES_X)   // 12288
#define NPIX 12582912.0f

#define C1 1.0e-4f
#define C2 9.0e-4f

#define N_V (TY * VS)               // 1200 u64 per buffer (9.6KB)

__device__ float g_partials[NBLOCKS];
__device__ unsigned g_ticket = 0;

// Normalized 1D Gaussian, window=11, sigma=1.5
__device__ __forceinline__ constexpr float Wt(int k) {
    constexpr float w[11] = {
        0.00102838f, 0.00759877f, 0.03600081f, 0.10936072f, 0.21300553f,
        0.26601169f,
        0.21300553f, 0.10936072f, 0.03600081f, 0.00759877f, 0.00102838f
    };
    return w[k];
}

// ---- f32x2 packed helpers ----
__device__ __forceinline__ u64 pk(float lo, float hi) {
    u64 r; asm("mov.b64 %0, {%1, %2};" : "=l"(r) : "f"(lo), "f"(hi)); return r;
}
__device__ __forceinline__ float2 upk(u64 v) {
    float2 r; asm("mov.b64 {%0, %1}, %2;" : "=f"(r.x), "=f"(r.y) : "l"(v)); return r;
}
__device__ __forceinline__ u64 fma2(u64 a, u64 b, u64 c) {
    u64 d; asm("fma.rn.f32x2 %0, %1, %2, %3;" : "=l"(d) : "l"(a), "l"(b), "l"(c)); return d;
}
__device__ __forceinline__ u64 mul2(u64 a, u64 b) {
    u64 d; asm("mul.rn.f32x2 %0, %1, %2;" : "=l"(d) : "l"(a), "l"(b)); return d;
}
__device__ __forceinline__ u64 wsel(const u64 (&w)[6], int k) {
    return w[k < 6 ? k : 10 - k];
}

// Vertical-blur task: WIN input rows -> NOUT output rows for column c.
// Per-task guards: x-out -> zeros; y-window inside -> fast; else y-guarded.
template<int WIN, int NOUT>
__device__ __forceinline__ void vtask(
    const float* __restrict__ p_plane, const float* __restrict__ t_plane,
    int gx, int gybase,
    u64* __restrict__ s_VA, u64* __restrict__ s_VB,
    int y0, int c, const u64 (&w2)[6])
{
    if ((unsigned)gx >= IMG) {          // whole column out of image -> zeros
        #pragma unroll
        for (int j = 0; j < NOUT; j++) {
            s_VA[(y0 + j) * VS + c] = 0ull;
            s_VB[(y0 + j) * VS + c] = 0ull;
        }
        return;
    }

    u64 a[WIN];
    if ((unsigned)gybase <= (IMG - WIN)) {   // fast path: window fully inside
        const float* pp = p_plane + (long)gybase * IMG + gx;
        const float* tp = t_plane + (long)gybase * IMG + gx;
        #pragma unroll
        for (int i = 0; i < WIN; i++)
            a[i] = pk(__ldg(pp + i * IMG), __ldg(tp + i * IMG));
    } else {
        #pragma unroll
        for (int i = 0; i < WIN; i++) {
            int gy = gybase + i;
            float pv = 0.0f, tv = 0.0f;
            if ((unsigned)gy < IMG) {
                long o = (long)gy * IMG + gx;
                pv = __ldg(p_plane + o);
                tv = __ldg(t_plane + o);
            }
            a[i] = pk(pv, tv);
        }
    }
    #pragma unroll
    for (int j = 0; j < NOUT; j++) {
        u64 acc = mul2(wsel(w2, 0), a[j]);
        #pragma unroll
        for (int k = 1; k < 11; k++) acc = fma2(wsel(w2, k), a[j + k], acc);
        s_VA[(y0 + j) * VS + c] = acc;
    }
    #pragma unroll
    for (int i = 0; i < WIN; i++) {     // (p,t) -> (p^2+t^2, p*t)
        float2 v = upk(a[i]);
        a[i] = pk(fmaf(v.x, v.x, v.y * v.y), v.x * v.y);
    }
    #pragma unroll
    for (int j = 0; j < NOUT; j++) {
        u64 acc = mul2(wsel(w2, 0), a[j]);
        #pragma unroll
        for (int k = 1; k < 11; k++) acc = fma2(wsel(w2, k), a[j + k], acc);
        s_VB[(y0 + j) * VS + c] = acc;
    }
}

__global__ __launch_bounds__(NTHREADS, 5)
void ssim_tile_kernel(const float* __restrict__ pred,
                      const float* __restrict__ targ,
                      float* __restrict__ out) {
    __shared__ u64 s_VA[N_V];     // V-blurred (mu_p, mu_t)
    __shared__ u64 s_VB[N_V];     // V-blurred (E[p^2]+E[t^2], E[pt])
    __shared__ float s_warp[8];
    __shared__ int   s_last;

    const int tid = threadIdx.x;
    const int ox = blockIdx.x * TX;
    const int oy = blockIdx.y * TY;
    const long plane_base = (long)blockIdx.z * (IMG * IMG);
    const float* __restrict__ p_plane = pred + plane_base;
    const float* __restrict__ t_plane = targ + plane_base;

    u64 w2[6];
    #pragma unroll
    for (int k = 0; k < 6; k++) w2[k] = pk(Wt(k), Wt(k));

    // ---- Phase 1: vertical blur from global. SINGLE round.
    // 148 tasks = 74 halo-cols x 2 row-groups of 8 outputs (window 18).
    if (tid < INW * 2) {
        int c = tid % INW;
        int g = tid / INW;
        int gx = ox + c - HALO;
        int y0 = 8 * g;
        vtask<18, 8>(p_plane, t_plane, gx,
                     oy + y0 - HALO, s_VA, s_VB, y0, c, w2);
    }
    __syncthreads();

    // ---- Phase 2: horizontal blur + SSIM. SINGLE round: 256 tasks of 4 cols.
    // r = tid & 15 (16 rows), grp = tid >> 4 (16 col-groups of 4).
    float local = 0.0f;
    {
        const int r = tid & 15;
        const int grp = tid >> 4;               // 0..15
        const int base = r * VS + 4 * grp;

        u64 amu[4];
        {
            u64 h[14];
            #pragma unroll
            for (int i = 0; i < 14; i++) h[i] = s_VA[base + i];
            #pragma unroll
            for (int j = 0; j < 4; j++) {
                u64 acc = mul2(wsel(w2, 0), h[j]);
                #pragma unroll
                for (int k = 1; k < 11; k++) acc = fma2(wsel(w2, k), h[j + k], acc);
                amu[j] = acc;
            }
        }
        u64 asb[4];
        {
            u64 h[14];
            #pragma unroll
            for (int i = 0; i < 14; i++) h[i] = s_VB[base + i];
            #pragma unroll
            for (int j = 0; j < 4; j++) {
                u64 acc = mul2(wsel(w2, 0), h[j]);
                #pragma unroll
                for (int k = 1; k < 11; k++) acc = fma2(wsel(w2, k), h[j + k], acc);
                asb[j] = acc;
            }
        }
        #pragma unroll
        for (int j = 0; j < 4; j++) {
            float2 mu = upk(amu[j]);
            float2 sb = upk(asb[j]);        // (E[p^2]+E[t^2], E[pt])
            float mu_p2 = mu.x * mu.x;
            float mu_t2 = mu.y * mu.y;
            float mu_pt = mu.x * mu.y;
            float num = (2.0f * mu_pt + C1) * (2.0f * (sb.y - mu_pt) + C2);
            float den = (mu_p2 + mu_t2 + C1) * ((sb.x - mu_p2 - mu_t2) + C2);
            local += __fdividef(num, den);
        }
    }

    // ---- Phase 3: block reduction ----
    float v = local;
    #pragma unroll
    for (int off = 16; off; off >>= 1)
        v += __shfl_xor_sync(0xFFFFFFFFu, v, off);
    if ((tid & 31) == 0) s_warp[tid >> 5] = v;
    __syncthreads();
    if (tid < 8) {
        v = s_warp[tid];
        #pragma unroll
        for (int off = 4; off; off >>= 1)
            v += __shfl_xor_sync(0x000000FFu, v, off);
    }
    if (tid == 0) {
        int bl = (blockIdx.z * TILES_Y + blockIdx.y) * TILES_X + blockIdx.x;
        g_partials[bl] = v;
        __threadfence();
        unsigned t = atomicInc(&g_ticket, NBLOCKS - 1);  // wraps -> self-reset
        s_last = (t == NBLOCKS - 1);
    }
    __syncthreads();

    // ---- Phase 4: last block folds partials (fixed order, deterministic) ----
    if (s_last) {
        float s = 0.0f;
        for (int i = tid; i < NBLOCKS; i += NTHREADS)
            s += __ldcg(&g_partials[i]);
        #pragma unroll
        for (int off = 16; off; off >>= 1)
            s += __shfl_xor_sync(0xFFFFFFFFu, s, off);
        if ((tid & 31) == 0) s_warp[tid >> 5] = s;
        __syncthreads();
        if (tid < 8) {
            s = s_warp[tid];
            #pragma unroll
            for (int off = 4; off; off >>= 1)
                s += __shfl_xor_sync(0x000000FFu, s, off);
            if (tid == 0) out[0] = 1.0f - s * (1.0f / NPIX);
        }
    }
}

extern "C" void kernel_launch(void* const* d_in, const int* in_sizes, int n_in,
                              void* d_out, int out_size) {
    const float* pred = (const float*)d_in[0];
    const float* targ = (const float*)d_in[1];
    float* out = (float*)d_out;

    dim3 grid(TILES_X, TILES_Y, PLANES);
    ssim_tile_kernel<<<grid, NTHREADS>>>(pred, targ, out);
}

// round 16
// speedup vs baseline: 1.2044x; 1.1787x over previous
#include <cuda_runtime.h>

// SSIM loss — R16: R13 verbatim (128x16 tiles, 5 blocks/SM, per-task guards,
// two-field algebra) + PACKED f32x2 SSIM epilogue (13 -> 7 fma-pipe ops/px).

typedef unsigned long long u64;

#define TX 128
#define TY 16
#define HALO 5
#define INW 138                     // TX + 2*HALO
#define VS 139                      // u64 stride (odd; 139 mod 16 = 11 -> conflict-free)
#define NTHREADS 256
#define IMG 512
#define TILES_X 4
#define TILES_Y 32
#define PLANES 48
#define NBLOCKS (PLANES * TILES_Y * TILES_X)   // 6144
#define NPIX 12582912.0f

#define C1 1.0e-4f
#define C2 9.0e-4f

#define N_V (TY * VS)               // 2224 u64 per buffer

__device__ float g_partials[NBLOCKS];
__device__ unsigned g_ticket = 0;

// Normalized 1D Gaussian, window=11, sigma=1.5
__device__ __forceinline__ constexpr float Wt(int k) {
    constexpr float w[11] = {
        0.00102838f, 0.00759877f, 0.03600081f, 0.10936072f, 0.21300553f,
        0.26601169f,
        0.21300553f, 0.10936072f, 0.03600081f, 0.00759877f, 0.00102838f
    };
    return w[k];
}

// ---- f32x2 packed helpers ----
__device__ __forceinline__ u64 pk(float lo, float hi) {
    u64 r; asm("mov.b64 %0, {%1, %2};" : "=l"(r) : "f"(lo), "f"(hi)); return r;
}
__device__ __forceinline__ float2 upk(u64 v) {
    float2 r; asm("mov.b64 {%0, %1}, %2;" : "=f"(r.x), "=f"(r.y) : "l"(v)); return r;
}
__device__ __forceinline__ u64 fma2(u64 a, u64 b, u64 c) {
    u64 d; asm("fma.rn.f32x2 %0, %1, %2, %3;" : "=l"(d) : "l"(a), "l"(b), "l"(c)); return d;
}
__device__ __forceinline__ u64 mul2(u64 a, u64 b) {
    u64 d; asm("mul.rn.f32x2 %0, %1, %2;" : "=l"(d) : "l"(a), "l"(b)); return d;
}
__device__ __forceinline__ u64 wsel(const u64 (&w)[6], int k) {
    return w[k < 6 ? k : 10 - k];
}

// Vertical-blur task: WIN input rows -> NOUT output rows for column c.
// Per-task guards: x-out -> zeros; y-window inside -> fast; else y-guarded.
template<int WIN, int NOUT>
__device__ __forceinline__ void vtask(
    const float* __restrict__ p_plane, const float* __restrict__ t_plane,
    int gx, int gybase,
    u64* __restrict__ s_VA, u64* __restrict__ s_VB,
    int y0, int c, const u64 (&w2)[6])
{
    if ((unsigned)gx >= IMG) {          // whole column out of image -> zeros
        #pragma unroll
        for (int j = 0; j < NOUT; j++) {
            s_VA[(y0 + j) * VS + c] = 0ull;
            s_VB[(y0 + j) * VS + c] = 0ull;
        }
        return;
    }

    u64 a[WIN];
    if ((unsigned)gybase <= (IMG - WIN)) {   // fast path: window fully inside
        const float* pp = p_plane + (long)gybase * IMG + gx;
        const float* tp = t_plane + (long)gybase * IMG + gx;
        #pragma unroll
        for (int i = 0; i < WIN; i++)
            a[i] = pk(__ldg(pp + i * IMG), __ldg(tp + i * IMG));
    } else {
        #pragma unroll
        for (int i = 0; i < WIN; i++) {
            int gy = gybase + i;
            float pv = 0.0f, tv = 0.0f;
            if ((unsigned)gy < IMG) {
                long o = (long)gy * IMG + gx;
                pv = __ldg(p_plane + o);
                tv = __ldg(t_plane + o);
            }
            a[i] = pk(pv, tv);
        }
    }
    #pragma unroll
    for (int j = 0; j < NOUT; j++) {
        u64 acc = mul2(wsel(w2, 0), a[j]);
        #pragma unroll
        for (int k = 1; k < 11; k++) acc = fma2(wsel(w2, k), a[j + k], acc);
        s_VA[(y0 + j) * VS + c] = acc;
    }
    #pragma unroll
    for (int i = 0; i < WIN; i++) {     // (p,t) -> (p^2+t^2, p*t)
        float2 v = upk(a[i]);
        a[i] = pk(fmaf(v.x, v.x, v.y * v.y), v.x * v.y);
    }
    #pragma unroll
    for (int j = 0; j < NOUT; j++) {
        u64 acc = mul2(wsel(w2, 0), a[j]);
        #pragma unroll
        for (int k = 1; k < 11; k++) acc = fma2(wsel(w2, k), a[j + k], acc);
        s_VB[(y0 + j) * VS + c] = acc;
    }
}

__global__ __launch_bounds__(NTHREADS, 5)
void ssim_tile_kernel(const float* __restrict__ pred,
                      const float* __restrict__ targ,
                      float* __restrict__ out) {
    __shared__ u64 s_VA[N_V];     // V-blurred (mu_p, mu_t)
    __shared__ u64 s_VB[N_V];     // V-blurred (E[p^2]+E[t^2], E[pt])
    __shared__ float s_warp[8];
    __shared__ int   s_last;

    const int tid = threadIdx.x;
    const int ox = blockIdx.x * TX;
    const int oy = blockIdx.y * TY;
    const long plane_base = (long)blockIdx.z * (IMG * IMG);
    const float* __restrict__ p_plane = pred + plane_base;
    const float* __restrict__ t_plane = targ + plane_base;

    u64 w2[6];
    #pragma unroll
    for (int k = 0; k < 6; k++) w2[k] = pk(Wt(k), Wt(k));

    // ---- Phase 1: vertical blur from global.
    // 276 tasks = 138 halo-cols x 2 row-groups of 8 outputs (window 18).
    #pragma unroll 1
    for (int it = 0; it < 2; it++) {
        int task = tid + it * NTHREADS;
        if (task < INW * 2) {
            int c = task % INW;
            int g = task / INW;
            int gx = ox + c - HALO;
            int y0 = 8 * g;
            vtask<18, 8>(p_plane, t_plane, gx,
                         oy + y0 - HALO, s_VA, s_VB, y0, c, w2);
        }
    }
    __syncthreads();

    // ---- Phase 2: horizontal blur + SSIM. 512 tasks of 4 cols, 2 rounds.
    float local = 0.0f;
    #pragma unroll
    for (int it = 0; it < 2; it++) {
        const int task = tid + it * NTHREADS;   // 0..511
        const int r = task & 15;
        const int grp = task >> 4;              // 0..31
        const int base = r * VS + 4 * grp;

        u64 amu[4];
        {
            u64 h[14];
            #pragma unroll
            for (int i = 0; i < 14; i++) h[i] = s_VA[base + i];
            #pragma unroll
            for (int j = 0; j < 4; j++) {
                u64 acc = mul2(wsel(w2, 0), h[j]);
                #pragma unroll
                for (int k = 1; k < 11; k++) acc = fma2(wsel(w2, k), h[j + k], acc);
                amu[j] = acc;
            }
        }
        u64 asb[4];
        {
            u64 h[14];
            #pragma unroll
            for (int i = 0; i < 14; i++) h[i] = s_VB[base + i];
            #pragma unroll
            for (int j = 0; j < 4; j++) {
                u64 acc = mul2(wsel(w2, 0), h[j]);
                #pragma unroll
                for (int k = 1; k < 11; k++) acc = fma2(wsel(w2, k), h[j + k], acc);
                asb[j] = acc;
            }
        }
        // Packed epilogue: num/den factor pairs ride in f32x2 lanes.
        //   a  = (mu_pt, q)              q = mu_p^2 + mu_t^2
        //   f1 = (2,1)*a + (C1,C1)       = (2*mu_pt+C1, q+C1)
        //   f2 = (-2,-1)*a + [(2,1)*(P,S) + (C2,C2)]
        //      = (2P+C2-2*mu_pt, S+C2-q)
        //   (num, den) = f1 * f2
        const u64 k21  = pk(2.0f, 1.0f);
        const u64 km21 = pk(-2.0f, -1.0f);
        const u64 kc1  = pk(C1, C1);
        const u64 kc2  = pk(C2, C2);
        #pragma unroll
        for (int j = 0; j < 4; j++) {
            float2 mu = upk(amu[j]);
            float2 sb = upk(asb[j]);        // (S = E[p^2]+E[t^2], P = E[pt])
            float mu_pt = mu.x * mu.y;
            float q = fmaf(mu.x, mu.x, mu.y * mu.y);
            u64 a  = pk(mu_pt, q);
            u64 f1 = fma2(k21, a, kc1);
            u64 f2 = fma2(km21, a, fma2(k21, pk(sb.y, sb.x), kc2));
            float2 nd = upk(mul2(f1, f2));
            local += __fdividef(nd.x, nd.y);
        }
    }

    // ---- Phase 3: block reduction ----
    float v = local;
    #pragma unroll
    for (int off = 16; off; off >>= 1)
        v += __shfl_xor_sync(0xFFFFFFFFu, v, off);
    if ((tid & 31) == 0) s_warp[tid >> 5] = v;
    __syncthreads();
    if (tid < 8) {
        v = s_warp[tid];
        #pragma unroll
        for (int off = 4; off; off >>= 1)
            v += __shfl_xor_sync(0x000000FFu, v, off);
    }
    if (tid == 0) {
        int bl = (blockIdx.z * TILES_Y + blockIdx.y) * TILES_X + blockIdx.x;
        g_partials[bl] = v;
        __threadfence();
        unsigned t = atomicInc(&g_ticket, NBLOCKS - 1);  // wraps -> self-reset
        s_last = (t == NBLOCKS - 1);
    }
    __syncthreads();

    // ---- Phase 4: last block folds partials (fixed order, deterministic) ----
    if (s_last) {
        float s = 0.0f;
        for (int i = tid; i < NBLOCKS; i += NTHREADS)
            s += __ldcg(&g_partials[i]);
        #pragma unroll
        for (int off = 16; off; off >>= 1)
            s += __shfl_xor_sync(0xFFFFFFFFu, s, off);
        if ((tid & 31) == 0) s_warp[tid >> 5] = s;
        __syncthreads();
        if (tid < 8) {
            s = s_warp[tid];
            #pragma unroll
            for (int off = 4; off; off >>= 1)
                s += __shfl_xor_sync(0x000000FFu, s, off);
            if (tid == 0) out[0] = 1.0f - s * (1.0f / NPIX);
        }
    }
}

extern "C" void kernel_launch(void* const* d_in, const int* in_sizes, int n_in,
                              void* d_out, int out_size) {
    const float* pred = (const float*)d_in[0];
    const float* targ = (const float*)d_in[1];
    float* out = (float*)d_out;

    dim3 grid(TILES_X, TILES_Y, PLANES);
    ssim_tile_kernel<<<grid, NTHREADS>>>(pred, targ, out);
}